// round 1
// baseline (speedup 1.0000x reference)
#include <cuda_runtime.h>
#include <cstdint>

// Problem constants (ResidualVQ_46935402611149)
#define B_ROWS 65536
#define DDIM   512
#define QSTAGES 8
#define KCODES 1024

// Scratch (no dynamic allocation allowed)
__device__ int                g_idx[B_ROWS];
__device__ float              g_cnorm[QSTAGES * KCODES];
__device__ double             g_loss[QSTAGES];

// ---------------------------------------------------------------------------
// helpers
// ---------------------------------------------------------------------------
__device__ __forceinline__ unsigned f2ord(float f) {
    unsigned u = __float_as_uint(f);
    return (u & 0x80000000u) ? ~u : (u | 0x80000000u);
}

// ---------------------------------------------------------------------------
// zero y_hat region of out + loss accumulators
// ---------------------------------------------------------------------------
__global__ void zero_kernel(float* __restrict__ yhat) {
    long long i = (long long)blockIdx.x * blockDim.x + threadIdx.x;
    long long stride = (long long)gridDim.x * blockDim.x;
    long long n = (long long)B_ROWS * DDIM;
    for (; i < n; i += stride) yhat[i] = 0.0f;
    if (blockIdx.x == 0 && threadIdx.x < QSTAGES) g_loss[threadIdx.x] = 0.0;
}

// ---------------------------------------------------------------------------
// code norms: ||c||^2 for all Q*K codes.  One warp per code.
// ---------------------------------------------------------------------------
__global__ void cnorm_kernel(const float* __restrict__ cb) {
    int warp = (blockIdx.x * blockDim.x + threadIdx.x) >> 5;
    int lane = threadIdx.x & 31;
    if (warp >= QSTAGES * KCODES) return;
    const float4* c = (const float4*)(cb + (long long)warp * DDIM);
    float s = 0.0f;
    for (int j = lane; j < DDIM / 4; j += 32) {
        float4 v = __ldg(c + j);
        s += v.x * v.x + v.y * v.y + v.z * v.z + v.w * v.w;
    }
    #pragma unroll
    for (int o = 16; o > 0; o >>= 1) s += __shfl_down_sync(0xFFFFFFFFu, s, o);
    if (lane == 0) g_cnorm[warp] = s;
}

// ---------------------------------------------------------------------------
// distance GEMM + fused argmin.
// BM=128 rows per block, full KCODES swept in BN=128 tiles, BK=16.
// residual = y - yhat reconstructed on the fly.
// d' = ||c||^2 - 2 * (r . c)  (per-row constant ||r||^2 dropped: same argmin)
// ---------------------------------------------------------------------------
#define BM 128
#define BN 128
#define BK 16
#define PAD 4

__global__ void __launch_bounds__(256, 2) argmin_kernel(
    const float* __restrict__ y, const float* __restrict__ yhat,
    const float* __restrict__ cb,      // this stage's codebook (K x D)
    int stage,
    float* __restrict__ idxf_out)      // may be null
{
    __shared__ float As[BK][BM + PAD];
    __shared__ float Bs[BK][BN + PAD];
    __shared__ unsigned long long skey[BM];

    const int tid  = threadIdx.x;
    const int row0 = blockIdx.x * BM;
    const int tm   = tid >> 4;   // 0..15 : row micro-group
    const int tn   = tid & 15;   // 0..15 : col micro-group

    if (tid < BM) skey[tid] = 0xFFFFFFFFFFFFFFFFull;

    const float* cn = g_cnorm + stage * KCODES;

    float acc[8][8];

    for (int nt = 0; nt < KCODES / BN; ++nt) {
        #pragma unroll
        for (int i = 0; i < 8; ++i)
            #pragma unroll
            for (int j = 0; j < 8; ++j) acc[i][j] = 0.0f;

        for (int kt = 0; kt < DDIM / BK; ++kt) {
            // load A tile (residual) : 128 x 16, float4 per thread x2
            #pragma unroll
            for (int it = 0; it < 2; ++it) {
                int l  = it * 256 + tid;       // 0..511
                int m  = l >> 2;               // 0..127
                int kq = (l & 3) * 4;          // 0,4,8,12
                long long ga = (long long)(row0 + m) * DDIM + kt * BK + kq;
                float4 a = __ldg((const float4*)(y + ga));
                float4 h = *(const float4*)(yhat + ga);
                As[kq + 0][m] = a.x - h.x;
                As[kq + 1][m] = a.y - h.y;
                As[kq + 2][m] = a.z - h.z;
                As[kq + 3][m] = a.w - h.w;
            }
            // load B tile (codes) : 128 x 16
            #pragma unroll
            for (int it = 0; it < 2; ++it) {
                int l  = it * 256 + tid;
                int m  = l >> 2;
                int kq = (l & 3) * 4;
                long long gb = (long long)(nt * BN + m) * DDIM + kt * BK + kq;
                float4 b = __ldg((const float4*)(cb + gb));
                Bs[kq + 0][m] = b.x;
                Bs[kq + 1][m] = b.y;
                Bs[kq + 2][m] = b.z;
                Bs[kq + 3][m] = b.w;
            }
            __syncthreads();

            #pragma unroll
            for (int k = 0; k < BK; ++k) {
                float af[8], bf[8];
                float4 a0 = *(const float4*)(&As[k][tm * 8]);
                float4 a1 = *(const float4*)(&As[k][tm * 8 + 4]);
                float4 b0 = *(const float4*)(&Bs[k][tn * 8]);
                float4 b1 = *(const float4*)(&Bs[k][tn * 8 + 4]);
                af[0]=a0.x; af[1]=a0.y; af[2]=a0.z; af[3]=a0.w;
                af[4]=a1.x; af[5]=a1.y; af[6]=a1.z; af[7]=a1.w;
                bf[0]=b0.x; bf[1]=b0.y; bf[2]=b0.z; bf[3]=b0.w;
                bf[4]=b1.x; bf[5]=b1.y; bf[6]=b1.z; bf[7]=b1.w;
                #pragma unroll
                for (int i = 0; i < 8; ++i)
                    #pragma unroll
                    for (int j = 0; j < 8; ++j)
                        acc[i][j] = fmaf(af[i], bf[j], acc[i][j]);
            }
            __syncthreads();
        }

        // epilogue: per-row local argmin over 8 codes, then shared atomicMin
        #pragma unroll
        for (int i = 0; i < 8; ++i) {
            unsigned long long best = 0xFFFFFFFFFFFFFFFFull;
            #pragma unroll
            for (int j = 0; j < 8; ++j) {
                int code = nt * BN + tn * 8 + j;
                float d = __ldg(cn + code) - 2.0f * acc[i][j];
                unsigned long long key =
                    ((unsigned long long)f2ord(d) << 32) | (unsigned)code;
                if (key < best) best = key;
            }
            atomicMin(&skey[tm * 8 + i], best);
        }
    }

    __syncthreads();
    if (tid < BM) {
        int idx = (int)(skey[tid] & 0xFFFFFFFFull);
        int row = row0 + tid;
        g_idx[row] = idx;
        if (idxf_out) idxf_out[(long long)row * QSTAGES + stage] = (float)idx;
    }
}

// ---------------------------------------------------------------------------
// gather + y_hat update + commitment loss.  8 rows per block, 32 thr/row.
// ---------------------------------------------------------------------------
__global__ void __launch_bounds__(256) update_kernel(
    const float* __restrict__ y, float* __restrict__ yhat,
    const float* __restrict__ cb, int stage)
{
    int tid  = threadIdx.x;
    int row  = blockIdx.x * 8 + (tid >> 5);
    int lane = tid & 31;
    int code = g_idx[row];

    const float4* cq = (const float4*)(cb + (long long)code * DDIM);
    const float4* yy = (const float4*)(y + (long long)row * DDIM);
    float4*       yh = (float4*)(yhat + (long long)row * DDIM);

    float s = 0.0f;
    #pragma unroll
    for (int j = lane; j < DDIM / 4; j += 32) {
        float4 q = __ldg(cq + j);
        float4 a = __ldg(yy + j);
        float4 h = yh[j];
        float rx = a.x - h.x, ry = a.y - h.y, rz = a.z - h.z, rw = a.w - h.w;
        float dx = q.x - rx, dy = q.y - ry, dz = q.z - rz, dw = q.w - rw;
        s += dx * dx + dy * dy + dz * dz + dw * dw;
        h.x += q.x; h.y += q.y; h.z += q.z; h.w += q.w;
        yh[j] = h;
    }
    #pragma unroll
    for (int o = 16; o > 0; o >>= 1) s += __shfl_down_sync(0xFFFFFFFFu, s, o);

    __shared__ float ws[8];
    if (lane == 0) ws[tid >> 5] = s;
    __syncthreads();
    if (tid == 0) {
        float t = 0.0f;
        #pragma unroll
        for (int w = 0; w < 8; ++w) t += ws[w];
        atomicAdd(&g_loss[stage], (double)t);
    }
}

// ---------------------------------------------------------------------------
// finalize: losses + loss_vq
// ---------------------------------------------------------------------------
__global__ void finalize_kernel(float* __restrict__ out, int extra) {
    if (threadIdx.x == 0 && extra) {
        const double inv = 1.0 / ((double)B_ROWS * DDIM);
        long long base = (long long)B_ROWS * DDIM + (long long)B_ROWS * QSTAGES;
        double m = 0.0;
        for (int i = 0; i < QSTAGES; ++i) {
            double li = g_loss[i] * inv;
            out[base + 1 + i] = (float)li;
            m += li;
        }
        out[base] = (float)(m / QSTAGES);
    }
}

// ---------------------------------------------------------------------------
extern "C" void kernel_launch(void* const* d_in, const int* in_sizes, int n_in,
                              void* d_out, int out_size)
{
    const float* y  = (const float*)d_in[0];
    const float* cb = (const float*)d_in[1];
    float* out  = (float*)d_out;
    float* yhat = out;  // first B*D elements of output are y_hat

    long long need = (long long)B_ROWS * DDIM + (long long)B_ROWS * QSTAGES
                     + 1 + QSTAGES;
    int extra = ((long long)out_size >= need) ? 1 : 0;
    float* idxf = extra ? (out + (long long)B_ROWS * DDIM) : nullptr;

    zero_kernel<<<4096, 256>>>(yhat);
    cnorm_kernel<<<(QSTAGES * KCODES + 7) / 8, 256>>>(cb);

    for (int s = 0; s < QSTAGES; ++s) {
        const float* cbs = cb + (long long)s * KCODES * DDIM;
        argmin_kernel<<<B_ROWS / BM, 256>>>(y, yhat, cbs, s, idxf);
        update_kernel<<<B_ROWS / 8, 256>>>(y, yhat, cbs, s);
    }
    finalize_kernel<<<1, 32>>>(out, extra);
}

// round 15
// speedup vs baseline: 1.0231x; 1.0231x over previous
#include <cuda_runtime.h>
#include <cstdint>

// Problem constants (ResidualVQ_46935402611149)
#define B_ROWS 65536
#define DDIM   512
#define QSTAGES 8
#define KCODES 1024

#define BM 128
#define BN 128
#define BK 16
#define PAD 4

// ---------------------------------------------------------------------------
// scratch (static device globals; no dynamic allocation)
// ---------------------------------------------------------------------------
__device__ __align__(16) float g_res[(size_t)B_ROWS * DDIM];   // 128 MB fp32 residual
__device__ int    g_idx[B_ROWS];
__device__ float  g_cnorm[QSTAGES * KCODES];
__device__ double g_loss[QSTAGES];

// ---------------------------------------------------------------------------
// helpers
// ---------------------------------------------------------------------------
__device__ __forceinline__ unsigned f2ord(float f) {
    unsigned u = __float_as_uint(f);
    return (u & 0x80000000u) ? ~u : (u | 0x80000000u);
}

// ---------------------------------------------------------------------------
// zero y_hat + loss accumulators
// ---------------------------------------------------------------------------
__global__ void zero_kernel(float* __restrict__ yhat) {
    long long i = (long long)blockIdx.x * blockDim.x + threadIdx.x;
    long long stride = (long long)gridDim.x * blockDim.x;
    long long n = (long long)B_ROWS * DDIM;
    for (; i < n; i += stride) yhat[i] = 0.0f;
    if (blockIdx.x == 0 && threadIdx.x < QSTAGES) g_loss[threadIdx.x] = 0.0;
}

// ---------------------------------------------------------------------------
// code norms (exact fp32)
// ---------------------------------------------------------------------------
__global__ void cnorm_kernel(const float* __restrict__ cb) {
    int warp = (blockIdx.x * blockDim.x + threadIdx.x) >> 5;
    int lane = threadIdx.x & 31;
    if (warp >= QSTAGES * KCODES) return;
    const float4* c = (const float4*)(cb + (long long)warp * DDIM);
    float s = 0.0f;
    for (int j = lane; j < DDIM / 4; j += 32) {
        float4 v = __ldg(c + j);
        s += v.x * v.x + v.y * v.y + v.z * v.z + v.w * v.w;
    }
    #pragma unroll
    for (int o = 16; o > 0; o >>= 1) s += __shfl_down_sync(0xFFFFFFFFu, s, o);
    if (lane == 0) g_cnorm[warp] = s;
}

// ---------------------------------------------------------------------------
// stage-0 residual = y
// ---------------------------------------------------------------------------
__global__ void prep_res_kernel(const float* __restrict__ y) {
    long long g = (long long)blockIdx.x * blockDim.x + threadIdx.x;
    if (g >= (long long)B_ROWS * DDIM / 4) return;
    long long i = g * 4;
    *(float4*)(g_res + i) = __ldg((const float4*)(y + i));
}

// ---------------------------------------------------------------------------
// exact fp32 distance GEMM + fused argmin, f32x2 (FFMA2) inner loop.
// BM=128 rows/CTA, all KCODES in BN=128 tiles, BK=16.
// d' = ||c||^2 - 2 * (r . c)   (per-row ||r||^2 dropped: same argmin)
// ---------------------------------------------------------------------------
__global__ void __launch_bounds__(256, 2) argmin_kernel(
    const float* __restrict__ cb,      // this stage's codebook (K x D)
    int stage,
    float* __restrict__ idxf)          // may be null
{
    __shared__ float As[BK][BM + PAD];
    __shared__ float Bs[BK][BN + PAD];
    __shared__ unsigned long long skey[BM];

    const int tid  = threadIdx.x;
    const int row0 = blockIdx.x * BM;
    const int tm   = tid >> 4;   // 0..15 : row micro-group
    const int tn   = tid & 15;   // 0..15 : col micro-group

    if (tid < BM) skey[tid] = 0xFFFFFFFFFFFFFFFFull;

    const float* cn = g_cnorm + stage * KCODES;

    const uint32_t sA = (uint32_t)__cvta_generic_to_shared(&As[0][0]);
    const uint32_t sB = (uint32_t)__cvta_generic_to_shared(&Bs[0][0]);
    const uint32_t aoff = sA + (uint32_t)tm * 32;   // byte offset of A micro-row
    const uint32_t boff = sB + (uint32_t)tn * 32;

    // packed f32x2 accumulators: acc[i2][j] = {row tm*8+2*i2, row tm*8+2*i2+1}
    unsigned long long acc[4][8];

    for (int nt = 0; nt < KCODES / BN; ++nt) {
        #pragma unroll
        for (int i2 = 0; i2 < 4; ++i2)
            #pragma unroll
            for (int j = 0; j < 8; ++j) acc[i2][j] = 0ull;

        for (int kt = 0; kt < DDIM / BK; ++kt) {
            // load A tile (residual) : 128 x 16
            #pragma unroll
            for (int it = 0; it < 2; ++it) {
                int l  = it * 256 + tid;       // 0..511
                int m  = l >> 2;               // 0..127
                int kq = (l & 3) * 4;          // 0,4,8,12
                long long ga = (long long)(row0 + m) * DDIM + kt * BK + kq;
                float4 a = *(const float4*)(g_res + ga);
                As[kq + 0][m] = a.x;
                As[kq + 1][m] = a.y;
                As[kq + 2][m] = a.z;
                As[kq + 3][m] = a.w;
            }
            // load B tile (codes) : 128 x 16
            #pragma unroll
            for (int it = 0; it < 2; ++it) {
                int l  = it * 256 + tid;
                int m  = l >> 2;
                int kq = (l & 3) * 4;
                long long gb = (long long)(nt * BN + m) * DDIM + kt * BK + kq;
                float4 b = __ldg((const float4*)(cb + gb));
                Bs[kq + 0][m] = b.x;
                Bs[kq + 1][m] = b.y;
                Bs[kq + 2][m] = b.z;
                Bs[kq + 3][m] = b.w;
            }
            __syncthreads();

            #pragma unroll
            for (int k = 0; k < BK; ++k) {
                const uint32_t arow = aoff + (uint32_t)k * ((BM + PAD) * 4);
                const uint32_t brow = boff + (uint32_t)k * ((BN + PAD) * 4);
                unsigned long long a2[4];
                uint32_t bf[8];
                asm volatile("ld.shared.v2.u64 {%0,%1}, [%2];"
                             : "=l"(a2[0]), "=l"(a2[1]) : "r"(arow));
                asm volatile("ld.shared.v2.u64 {%0,%1}, [%2];"
                             : "=l"(a2[2]), "=l"(a2[3]) : "r"(arow + 16));
                asm volatile("ld.shared.v4.u32 {%0,%1,%2,%3}, [%4];"
                             : "=r"(bf[0]), "=r"(bf[1]), "=r"(bf[2]), "=r"(bf[3])
                             : "r"(brow));
                asm volatile("ld.shared.v4.u32 {%0,%1,%2,%3}, [%4];"
                             : "=r"(bf[4]), "=r"(bf[5]), "=r"(bf[6]), "=r"(bf[7])
                             : "r"(brow + 16));
                unsigned long long bs[8];
                #pragma unroll
                for (int j = 0; j < 8; ++j)
                    asm("mov.b64 %0, {%1,%1};" : "=l"(bs[j]) : "r"(bf[j]));
                #pragma unroll
                for (int i2 = 0; i2 < 4; ++i2)
                    #pragma unroll
                    for (int j = 0; j < 8; ++j)
                        asm("fma.rn.f32x2 %0, %1, %2, %0;"
                            : "+l"(acc[i2][j]) : "l"(a2[i2]), "l"(bs[j]));
            }
            __syncthreads();
        }

        // epilogue: per-row local argmin over 8 codes, then shared atomicMin
        #pragma unroll
        for (int i2 = 0; i2 < 4; ++i2) {
            unsigned long long b_lo = 0xFFFFFFFFFFFFFFFFull;
            unsigned long long b_hi = 0xFFFFFFFFFFFFFFFFull;
            #pragma unroll
            for (int j = 0; j < 8; ++j) {
                uint32_t rlo, rhi;
                asm("mov.b64 {%0,%1}, %2;" : "=r"(rlo), "=r"(rhi) : "l"(acc[i2][j]));
                int code = nt * BN + tn * 8 + j;
                float cnv = __ldg(cn + code);
                float d0 = cnv - 2.0f * __uint_as_float(rlo);
                float d1 = cnv - 2.0f * __uint_as_float(rhi);
                unsigned long long k0 =
                    ((unsigned long long)f2ord(d0) << 32) | (unsigned)code;
                unsigned long long k1 =
                    ((unsigned long long)f2ord(d1) << 32) | (unsigned)code;
                if (k0 < b_lo) b_lo = k0;
                if (k1 < b_hi) b_hi = k1;
            }
            atomicMin(&skey[tm * 8 + 2 * i2],     b_lo);
            atomicMin(&skey[tm * 8 + 2 * i2 + 1], b_hi);
        }
    }

    __syncthreads();
    if (tid < BM) {
        int idx = (int)(skey[tid] & 0xFFFFFFFFull);
        int row = row0 + tid;
        g_idx[row] = idx;
        if (idxf) idxf[(long long)row * QSTAGES + stage] = (float)idx;
    }
}

// ---------------------------------------------------------------------------
// gather + y_hat update + commitment loss + residual update (fp32, exact)
// 8 rows per block, 32 thr/row.
// ---------------------------------------------------------------------------
__global__ void __launch_bounds__(256) update_kernel(
    float* __restrict__ yhat, const float* __restrict__ cb, int stage)
{
    int tid  = threadIdx.x;
    int row  = blockIdx.x * 8 + (tid >> 5);
    int lane = tid & 31;
    int code = g_idx[row];

    const float4* cq = (const float4*)(cb + (long long)code * DDIM);
    float4* rr = (float4*)(g_res + (long long)row * DDIM);
    float4* yh = (float4*)(yhat + (long long)row * DDIM);

    float s = 0.0f;
    #pragma unroll
    for (int j = lane; j < DDIM / 4; j += 32) {
        float4 q = __ldg(cq + j);
        float4 r = rr[j];
        float4 h = yh[j];
        float dx = q.x - r.x, dy = q.y - r.y, dz = q.z - r.z, dw = q.w - r.w;
        s += dx * dx + dy * dy + dz * dz + dw * dw;
        // next residual = r - q   (matches reference fp32 op order)
        r.x -= q.x; r.y -= q.y; r.z -= q.z; r.w -= q.w;
        rr[j] = r;
        h.x += q.x; h.y += q.y; h.z += q.z; h.w += q.w;
        yh[j] = h;
    }
    #pragma unroll
    for (int o = 16; o > 0; o >>= 1) s += __shfl_down_sync(0xFFFFFFFFu, s, o);

    __shared__ float ws[8];
    if (lane == 0) ws[tid >> 5] = s;
    __syncthreads();
    if (tid == 0) {
        float t = 0.0f;
        #pragma unroll
        for (int w = 0; w < 8; ++w) t += ws[w];
        atomicAdd(&g_loss[stage], (double)t);
    }
}

// ---------------------------------------------------------------------------
// finalize losses
// ---------------------------------------------------------------------------
__global__ void finalize_kernel(float* __restrict__ out, int extra) {
    if (threadIdx.x == 0 && extra) {
        const double inv = 1.0 / ((double)B_ROWS * DDIM);
        long long base = (long long)B_ROWS * DDIM + (long long)B_ROWS * QSTAGES;
        double m = 0.0;
        for (int i = 0; i < QSTAGES; ++i) {
            double li = g_loss[i] * inv;
            out[base + 1 + i] = (float)li;
            m += li;
        }
        out[base] = (float)(m / QSTAGES);
    }
}

// ---------------------------------------------------------------------------
extern "C" void kernel_launch(void* const* d_in, const int* in_sizes, int n_in,
                              void* d_out, int out_size)
{
    const float* y  = (const float*)d_in[0];
    const float* cb = (const float*)d_in[1];
    float* out  = (float*)d_out;
    float* yhat = out;  // first B*D elements of output are y_hat

    long long need = (long long)B_ROWS * DDIM + (long long)B_ROWS * QSTAGES
                     + 1 + QSTAGES;
    int extra = ((long long)out_size >= need) ? 1 : 0;
    float* idxf = extra ? (out + (long long)B_ROWS * DDIM) : nullptr;

    zero_kernel<<<4096, 256>>>(yhat);
    cnorm_kernel<<<(QSTAGES * KCODES + 7) / 8, 256>>>(cb);
    prep_res_kernel<<<(B_ROWS * DDIM / 4 + 255) / 256, 256>>>(y);

    for (int s = 0; s < QSTAGES; ++s) {
        const float* cbs = cb + (long long)s * KCODES * DDIM;
        argmin_kernel<<<B_ROWS / BM, 256>>>(cbs, s, idxf);
        update_kernel<<<B_ROWS / 8, 256>>>(yhat, cbs, s);
    }
    finalize_kernel<<<1, 32>>>(out, extra);
}